// round 7
// baseline (speedup 1.0000x reference)
#include <cuda_runtime.h>
#include <cstdint>

#define BATCH 4
#define SEQ   2048
#define DMODEL 1024

// Scratch (device globals — no cudaMalloc allowed)
__device__ float g_QKV[(size_t)3 * BATCH * SEQ * DMODEL];   // 96 MB (Q,K,V)
__device__ float g_P  [(size_t)BATCH * SEQ * SEQ];          // 64 MB (scores/probs)
__device__ float g_AO [(size_t)BATCH * SEQ * DMODEL];       // 32 MB
__device__ float g_X  [(size_t)BATCH * SEQ * DMODEL];       // 32 MB (tf32-rounded x)
__device__ float g_W  [(size_t)4 * DMODEL * DMODEL];        // 16 MB (WqT,WkT,WvT,WoT rounded)
__device__ float g_VT [(size_t)BATCH * SEQ * DMODEL];       // 32 MB (V transposed per batch)

__device__ __forceinline__ uint32_t f2tf32(float x) {
    uint32_t r;
    asm("cvt.rna.tf32.f32 %0, %1;" : "=r"(r) : "f"(x));
    return r;
}
__device__ __forceinline__ float rtf(float x) { return __uint_as_float(f2tf32(x)); }

__device__ __forceinline__ void mma8(float c[4], const uint32_t a[4], const uint32_t b[2]) {
    asm volatile(
        "mma.sync.aligned.m16n8k8.row.col.f32.tf32.tf32.f32 "
        "{%0,%1,%2,%3}, {%4,%5,%6,%7}, {%8,%9}, {%0,%1,%2,%3};\n"
        : "+f"(c[0]), "+f"(c[1]), "+f"(c[2]), "+f"(c[3])
        : "r"(a[0]), "r"(a[1]), "r"(a[2]), "r"(a[3]), "r"(b[0]), "r"(b[1]));
}

__device__ __forceinline__ void cpa16(float* dst, const float* src) {
    uint32_t d = (uint32_t)__cvta_generic_to_shared(dst);
    asm volatile("cp.async.cg.shared.global [%0], [%1], 16;\n" :: "r"(d), "l"(src));
}

// ldmatrix x4 over b16-typed tiles: for fp32/tf32 data each 8x8 b16 tile is an
// 8-row x 4-float tile; lane t receives row t/4, float-column t%4 as one .b32.
__device__ __forceinline__ void ldmx4(uint32_t r[4], const float* p) {
    uint32_t a = (uint32_t)__cvta_generic_to_shared(p);
    asm volatile("ldmatrix.sync.aligned.m8n8.x4.shared.b16 {%0,%1,%2,%3}, [%4];"
        : "=r"(r[0]), "=r"(r[1]), "=r"(r[2]), "=r"(r[3]) : "r"(a));
}

// ---------------- pre-pass kernels ----------------

__global__ void round_tf32(const float4* __restrict__ in, float4* __restrict__ out, int n4)
{
    int i = blockIdx.x * blockDim.x + threadIdx.x;
    if (i < n4) {
        float4 v = in[i];
        v.x = rtf(v.x); v.y = rtf(v.y); v.z = rtf(v.z); v.w = rtf(v.w);
        out[i] = v;
    }
}

// out[c*R + r] = (round? rtf : id)(in[r*C + c]); batch planes via blockIdx.z.
__global__ void transpose_round(const float* __restrict__ in, float* __restrict__ out,
                                int R, int C, size_t sIn, size_t sOut, int doRound)
{
    __shared__ float tile[32][33];
    in  += (size_t)blockIdx.z * sIn;
    out += (size_t)blockIdx.z * sOut;
    const int bx = blockIdx.x * 32;   // c
    const int by = blockIdx.y * 32;   // r
    const int tx = threadIdx.x, ty = threadIdx.y;
    #pragma unroll
    for (int i = 0; i < 32; i += 8)
        tile[ty + i][tx] = in[(size_t)(by + ty + i) * C + bx + tx];
    __syncthreads();
    #pragma unroll
    for (int i = 0; i < 32; i += 8) {
        float v = tile[tx][ty + i];
        out[(size_t)(bx + ty + i) * R + by + tx] = doRound ? rtf(v) : v;
    }
}

// ---------------- NT TF32 GEMM: C[M,N] = A[M,K] * B[N,K]^T ----------------
// CTA tile 128(M) x 256(N) x 16(K), 8 warps (2x4), warp tile 64x64.
// 4-stage cp.async pipeline; all fragments via ldmatrix; inputs pre-rounded.
//   TRIPLE: blockIdx.z selects B among {B0,B1,B2}, C += z*sC (QKV fusion)
//   mask: epilogue v*scale, masked -> -1e10 (int32 vs byte auto-probe)
//   roundC: round outputs to tf32.
template<bool TRIPLE>
__global__ __launch_bounds__(256, 1)
void gemm_nt(const float* __restrict__ A, const float* __restrict__ B0,
             const float* __restrict__ B1, const float* __restrict__ B2,
             float* __restrict__ C, int M, int N, int K,
             size_t sA, size_t sB, size_t sC,
             const unsigned char* __restrict__ mask, float scale, int roundC)
{
    constexpr int BM = 128, BN = 256, BK = 16;
    constexpr int RST = 20;                 // smem row stride (floats)
    constexpr int ASZ = BM * RST;           // 2560 floats
    constexpr int STG = (BM + BN) * RST;    // 7680 floats / stage
    constexpr int NSTAGE = 4;

    extern __shared__ float sm[];
    __shared__ int mask_is_int32;

    const int bz = blockIdx.z;
    const float* B;
    if (TRIPLE) {
        B = (bz == 0) ? B0 : (bz == 1 ? B1 : B2);
        C += (size_t)bz * sC;
    } else {
        B = B0 + (size_t)bz * sB;
        A += (size_t)bz * sA;
        C += (size_t)bz * sC;
    }

    const int bm = blockIdx.y * BM;
    const int bn = blockIdx.x * BN;
    const int t    = threadIdx.x;
    const int lane = t & 31;
    const int wid  = t >> 5;
    const int wm   = wid >> 2;        // 0..1  (M)
    const int wn   = wid & 3;         // 0..3  (N)
    const int g    = lane >> 2;       // 0..7
    const int tig  = lane & 3;        // 0..3

    if (mask && t == 0) {
        int is_int = 1;
        #pragma unroll 4
        for (int i = 0; i < 256; i++)
            if ((i & 3) != 0 && mask[i] != 0) is_int = 0;
        mask_is_int32 = is_int;
    }

    float acc[4][8][4];
    #pragma unroll
    for (int i = 0; i < 4; i++)
        #pragma unroll
        for (int j = 0; j < 8; j++)
            #pragma unroll
            for (int r = 0; r < 4; r++) acc[i][j][r] = 0.f;

    const int nkt = K / BK;

    auto issue = [&](int kt) {
        float* As = sm + (kt % NSTAGE) * STG;
        float* Bs = As + ASZ;
        const int kk = kt * BK;
        // A: 128 rows x 16 -> 512 float4 (2 rounds)
        #pragma unroll
        for (int h = 0; h < 2; h++) {
            const int c = h * 256 + t;
            const int r = c >> 2, kq = c & 3;
            cpa16(&As[r * RST + kq * 4], A + (size_t)(bm + r) * K + kk + kq * 4);
        }
        // B: 256 rows x 16 -> 1024 float4 (4 rounds)
        #pragma unroll
        for (int h = 0; h < 4; h++) {
            const int c = h * 256 + t;
            const int r = c >> 2, kq = c & 3;
            cpa16(&Bs[r * RST + kq * 4], B + (size_t)(bn + r) * K + kk + kq * 4);
        }
        asm volatile("cp.async.commit_group;\n");
    };

    issue(0); issue(1); issue(2);

    // ldmatrix per-lane selectors (constant across k-loop)
    const int a_row = (lane & 15);                       // row within 16-row group
    const int a_kof = (lane >> 4) << 2;                  // 0 or 4
    const int b_row = (lane & 7) + ((lane & 16) >> 1);   // row within 16-n group
    const int b_kof = (lane & 8) >> 1;                   // 0 or 4

    for (int kt = 0; kt < nkt; ++kt) {
        const int nw = nkt - 1 - kt;
        if (nw >= 2)      asm volatile("cp.async.wait_group 2;\n");
        else if (nw == 1) asm volatile("cp.async.wait_group 1;\n");
        else              asm volatile("cp.async.wait_group 0;\n");
        __syncthreads();

        if (kt + 3 < nkt) issue(kt + 3);

        const float* As = sm + (kt % NSTAGE) * STG;
        const float* Bs = As + ASZ;

        #pragma unroll
        for (int ks = 0; ks < 2; ++ks) {
            const int k0 = ks * 8;
            uint32_t af[4][4];
            uint32_t bf[8][2];
            #pragma unroll
            for (int i = 0; i < 4; i++) {
                const int rb = wm * 64 + i * 16;
                ldmx4(af[i], &As[(rb + a_row) * RST + k0 + a_kof]);
            }
            #pragma unroll
            for (int jp = 0; jp < 4; jp++) {
                uint32_t bq[4];
                const int nb = wn * 64 + jp * 16;
                ldmx4(bq, &Bs[(nb + b_row) * RST + k0 + b_kof]);
                bf[jp * 2][0]     = bq[0];
                bf[jp * 2][1]     = bq[1];
                bf[jp * 2 + 1][0] = bq[2];
                bf[jp * 2 + 1][1] = bq[3];
            }
            #pragma unroll
            for (int i = 0; i < 4; i++)
                #pragma unroll
                for (int j = 0; j < 8; j++)
                    mma8(acc[i][j], af[i], bf[j]);
        }
    }

    if (mask) __syncthreads();   // make mask_is_int32 visible

    // epilogue: warp covers 64x64 at (bm + wm*64, bn + wn*64)
    #pragma unroll
    for (int i = 0; i < 4; i++) {
        const int r0 = bm + wm * 64 + i * 16 + g;
        #pragma unroll
        for (int j = 0; j < 8; j++) {
            const int c0 = bn + wn * 64 + j * 8 + tig * 2;
            float v0 = acc[i][j][0], v1 = acc[i][j][1];
            float v2 = acc[i][j][2], v3 = acc[i][j][3];
            if (mask) {
                const size_t base = (size_t)bz * (size_t)M * N + (size_t)r0 * N;
                int m00, m01, m10, m11;
                if (mask_is_int32) {
                    const int* mi = (const int*)mask;
                    int2 ma = *(const int2*)&mi[base + c0];
                    int2 mb = *(const int2*)&mi[base + (size_t)8 * N + c0];
                    m00 = ma.x; m01 = ma.y; m10 = mb.x; m11 = mb.y;
                } else {
                    m00 = mask[base + c0];                   m01 = mask[base + c0 + 1];
                    m10 = mask[base + (size_t)8 * N + c0];   m11 = mask[base + (size_t)8 * N + c0 + 1];
                }
                v0 = m00 ? v0 * scale : -1e10f;
                v1 = m01 ? v1 * scale : -1e10f;
                v2 = m10 ? v2 * scale : -1e10f;
                v3 = m11 ? v3 * scale : -1e10f;
            }
            if (roundC) {
                v0 = rtf(v0); v1 = rtf(v1); v2 = rtf(v2); v3 = rtf(v3);
            }
            float2 w0 = {v0, v1}, w1 = {v2, v3};
            *(float2*)&C[(size_t)r0 * N + c0]       = w0;
            *(float2*)&C[(size_t)(r0 + 8) * N + c0] = w1;
        }
    }
}

// ---------------- softmax ----------------

__global__ void softmax2048(float* __restrict__ P)
{
    float* p = P + (size_t)blockIdx.x * 2048;
    const int t = threadIdx.x, lane = t & 31, wid = t >> 5;
    __shared__ float red[8];

    float4 v0 = ((const float4*)p)[t];
    float4 v1 = ((const float4*)p)[t + 256];

    float m = fmaxf(fmaxf(fmaxf(v0.x, v0.y), fmaxf(v0.z, v0.w)),
                    fmaxf(fmaxf(v1.x, v1.y), fmaxf(v1.z, v1.w)));
    #pragma unroll
    for (int o = 16; o; o >>= 1) m = fmaxf(m, __shfl_xor_sync(0xffffffffu, m, o));
    if (lane == 0) red[wid] = m;
    __syncthreads();
    float bm = red[0];
    #pragma unroll
    for (int w = 1; w < 8; w++) bm = fmaxf(bm, red[w]);
    __syncthreads();

    v0.x = __expf(v0.x - bm); v0.y = __expf(v0.y - bm);
    v0.z = __expf(v0.z - bm); v0.w = __expf(v0.w - bm);
    v1.x = __expf(v1.x - bm); v1.y = __expf(v1.y - bm);
    v1.z = __expf(v1.z - bm); v1.w = __expf(v1.w - bm);

    float s = v0.x + v0.y + v0.z + v0.w + v1.x + v1.y + v1.z + v1.w;
    #pragma unroll
    for (int o = 16; o; o >>= 1) s += __shfl_xor_sync(0xffffffffu, s, o);
    if (lane == 0) red[wid] = s;
    __syncthreads();
    float bs = red[0];
    #pragma unroll
    for (int w = 1; w < 8; w++) bs += red[w];

    const float inv = 1.f / bs;
    v0.x = rtf(v0.x * inv); v0.y = rtf(v0.y * inv);
    v0.z = rtf(v0.z * inv); v0.w = rtf(v0.w * inv);
    v1.x = rtf(v1.x * inv); v1.y = rtf(v1.y * inv);
    v1.z = rtf(v1.z * inv); v1.w = rtf(v1.w * inv);
    ((float4*)p)[t]       = v0;
    ((float4*)p)[t + 256] = v1;
}

// ---------------- host ----------------

extern "C" void kernel_launch(void* const* d_in, const int* in_sizes, int n_in,
                              void* d_out, int out_size)
{
    const float*         x    = (const float*)d_in[0];
    const unsigned char* mask = (const unsigned char*)d_in[1];
    const float*         Wq   = (const float*)d_in[2];
    const float*         Wk   = (const float*)d_in[3];
    const float*         Wv   = (const float*)d_in[4];
    const float*         Wo   = (const float*)d_in[5];
    float*               out  = (float*)d_out;

    float *QKV, *P, *AO, *X, *W, *VT;
    cudaGetSymbolAddress((void**)&QKV, g_QKV);
    cudaGetSymbolAddress((void**)&P,   g_P);
    cudaGetSymbolAddress((void**)&AO,  g_AO);
    cudaGetSymbolAddress((void**)&X,   g_X);
    cudaGetSymbolAddress((void**)&W,   g_W);
    cudaGetSymbolAddress((void**)&VT,  g_VT);

    const size_t pstride = (size_t)BATCH * SEQ * DMODEL;   // full Q/K/V plane
    const size_t bstride = (size_t)SEQ * DMODEL;           // per-batch plane
    const size_t wsz = (size_t)DMODEL * DMODEL;
    float* WqT = W;
    float* WkT = W + wsz;
    float* WvT = W + 2 * wsz;
    float* WoT = W + 3 * wsz;
    float* Q = QKV;
    float* Kp = QKV + pstride;
    float* V = QKV + 2 * pstride;

    // --- pre-pass: round x; transpose+round weights ---
    {
        const int xe4 = (int)(pstride / 4);
        round_tf32<<<(xe4 + 255) / 256, 256>>>((const float4*)x, (float4*)X, xe4);
        dim3 tb(32, 8);
        dim3 tg(DMODEL / 32, DMODEL / 32, 1);
        transpose_round<<<tg, tb>>>(Wq, WqT, DMODEL, DMODEL, 0, 0, 1);
        transpose_round<<<tg, tb>>>(Wk, WkT, DMODEL, DMODEL, 0, 0, 1);
        transpose_round<<<tg, tb>>>(Wv, WvT, DMODEL, DMODEL, 0, 0, 1);
        transpose_round<<<tg, tb>>>(Wo, WoT, DMODEL, DMODEL, 0, 0, 1);
    }

    const int smemB = 4 * 7680 * 4;   // 122880 B (4 stages)
    cudaFuncSetAttribute(gemm_nt<true>,
                         cudaFuncAttributeMaxDynamicSharedMemorySize, smemB);
    cudaFuncSetAttribute(gemm_nt<false>,
                         cudaFuncAttributeMaxDynamicSharedMemorySize, smemB);

    const int MS = BATCH * SEQ;   // 8192
    dim3 blk(256);

    // QKV projections fused: C[m,n] = X[m,k] * WT[n,k]
    dim3 gq(DMODEL / 256, MS / 128, 3);
    gemm_nt<true><<<gq, blk, smemB>>>(
        X, WqT, WkT, WvT, QKV, MS, DMODEL, DMODEL, 0, 0, pstride, nullptr, 1.f, 1);

    // V transpose per batch: VT[b][d][s] = V[b][s][d]
    {
        dim3 tb(32, 8);
        dim3 tg(DMODEL / 32, SEQ / 32, BATCH);
        transpose_round<<<tg, tb>>>(V, VT, SEQ, DMODEL, bstride, bstride, 0);
    }

    // scores = Q K^T / 32, masked
    dim3 gs(SEQ / 256, SEQ / 128, BATCH);
    gemm_nt<false><<<gs, blk, smemB>>>(
        Q, Kp, nullptr, nullptr, P, SEQ, SEQ, DMODEL,
        bstride, bstride, (size_t)SEQ * SEQ, mask, 0.03125f, 0);

    softmax2048<<<BATCH * SEQ, 256>>>(P);

    // attn_out = P * V  (B = VT[b] is [DMODEL rows, SEQ cols] K-major)
    dim3 gv(DMODEL / 256, SEQ / 128, BATCH);
    gemm_nt<false><<<gv, blk, smemB>>>(
        P, VT, nullptr, nullptr, AO, SEQ, DMODEL, SEQ,
        (size_t)SEQ * SEQ, bstride, bstride, nullptr, 1.f, 1);

    // output projection: out[m,n] = AO[m,k] * WoT[n,k]
    dim3 go(DMODEL / 256, MS / 128, 1);
    gemm_nt<false><<<go, blk, smemB>>>(
        AO, WoT, nullptr, nullptr, out, MS, DMODEL, DMODEL, 0, 0, 0, nullptr, 1.f, 0);
}

// round 8
// speedup vs baseline: 1.5044x; 1.5044x over previous
#include <cuda_runtime.h>
#include <cstdint>

#define BATCH 4
#define SEQ   2048
#define DMODEL 1024

// Scratch (device globals — no cudaMalloc allowed)
__device__ float g_QKV[(size_t)3 * BATCH * SEQ * DMODEL];   // 96 MB (Q,K,V)
__device__ float g_P  [(size_t)BATCH * SEQ * SEQ];          // 64 MB (scores/probs)
__device__ float g_AO [(size_t)BATCH * SEQ * DMODEL];       // 32 MB
__device__ float g_X  [(size_t)BATCH * SEQ * DMODEL];       // 32 MB (tf32-rounded x)
__device__ float g_W  [(size_t)4 * DMODEL * DMODEL];        // 16 MB (WqT,WkT,WvT,WoT rounded)
__device__ float g_VT [(size_t)BATCH * SEQ * DMODEL];       // 32 MB (V transposed per batch)

__device__ __forceinline__ uint32_t f2tf32(float x) {
    uint32_t r;
    asm("cvt.rna.tf32.f32 %0, %1;" : "=r"(r) : "f"(x));
    return r;
}
__device__ __forceinline__ float rtf(float x) { return __uint_as_float(f2tf32(x)); }

__device__ __forceinline__ void mma8(float c[4], const uint32_t a[4], const uint32_t b[2]) {
    asm volatile(
        "mma.sync.aligned.m16n8k8.row.col.f32.tf32.tf32.f32 "
        "{%0,%1,%2,%3}, {%4,%5,%6,%7}, {%8,%9}, {%0,%1,%2,%3};\n"
        : "+f"(c[0]), "+f"(c[1]), "+f"(c[2]), "+f"(c[3])
        : "r"(a[0]), "r"(a[1]), "r"(a[2]), "r"(a[3]), "r"(b[0]), "r"(b[1]));
}

__device__ __forceinline__ void cpa16s(uint32_t dst, const float* src) {
    asm volatile("cp.async.cg.shared.global [%0], [%1], 16;\n" :: "r"(dst), "l"(src));
}

__device__ __forceinline__ void ldmx4s(uint32_t r[4], uint32_t addr) {
    asm volatile("ldmatrix.sync.aligned.m8n8.x4.shared.b16 {%0,%1,%2,%3}, [%4];"
        : "=r"(r[0]), "=r"(r[1]), "=r"(r[2]), "=r"(r[3]) : "r"(addr));
}

// SW128-style XOR swizzle on byte offsets (16B granular): chunk ^= row%8
__device__ __forceinline__ uint32_t sw128(uint32_t off) {
    return off ^ ((off >> 3) & 0x70u);
}

// ---------------- pre-pass kernels ----------------

__global__ void round_tf32(const float4* __restrict__ in, float4* __restrict__ out, int n4)
{
    int i = blockIdx.x * blockDim.x + threadIdx.x;
    if (i < n4) {
        float4 v = in[i];
        v.x = rtf(v.x); v.y = rtf(v.y); v.z = rtf(v.z); v.w = rtf(v.w);
        out[i] = v;
    }
}

// out[c*R + r] = (round? rtf : id)(in[r*C + c]); batch planes via blockIdx.z.
__global__ void transpose_round(const float* __restrict__ in, float* __restrict__ out,
                                int R, int C, size_t sIn, size_t sOut, int doRound)
{
    __shared__ float tile[32][33];
    in  += (size_t)blockIdx.z * sIn;
    out += (size_t)blockIdx.z * sOut;
    const int bx = blockIdx.x * 32;   // c
    const int by = blockIdx.y * 32;   // r
    const int tx = threadIdx.x, ty = threadIdx.y;
    #pragma unroll
    for (int i = 0; i < 32; i += 8)
        tile[ty + i][tx] = in[(size_t)(by + ty + i) * C + bx + tx];
    __syncthreads();
    #pragma unroll
    for (int i = 0; i < 32; i += 8) {
        float v = tile[tx][ty + i];
        out[(size_t)(bx + ty + i) * R + by + tx] = doRound ? rtf(v) : v;
    }
}

// ---------------- NT TF32 GEMM: C[M,N] = A[M,K] * B[N,K]^T ----------------
// CTA tile 128x128x32, 4 warps (2x2), warp tile 64x64, 3-stage cp.async,
// XOR-swizzled smem (32KB/stage), ldmatrix fragments, inputs pre-rounded.
//   TRIPLE: blockIdx.z selects B among {B0,B1,B2}, C += z*sC (QKV fusion)
//   mask: epilogue v*scale, masked -> -1e10 (int32 vs byte auto-probe)
//   roundC: round outputs to tf32.
template<bool TRIPLE>
__global__ __launch_bounds__(128, 2)
void gemm_nt(const float* __restrict__ A, const float* __restrict__ B0,
             const float* __restrict__ B1, const float* __restrict__ B2,
             float* __restrict__ C, int M, int N, int K,
             size_t sA, size_t sB, size_t sC,
             const unsigned char* __restrict__ mask, float scale, int roundC)
{
    constexpr int BK = 32;
    constexpr uint32_t TILE_B = 128u * 128u;     // 16 KB per operand tile
    constexpr uint32_t STG_B  = 2u * TILE_B;     // 32 KB per stage
    constexpr int NSTAGE = 3;

    extern __shared__ float smf[];
    __shared__ int mask_is_int32;

    const int bz = blockIdx.z;
    const float* B;
    if (TRIPLE) {
        B = (bz == 0) ? B0 : (bz == 1 ? B1 : B2);
        C += (size_t)bz * sC;
    } else {
        B = B0 + (size_t)bz * sB;
        A += (size_t)bz * sA;
        C += (size_t)bz * sC;
    }

    const int bm = blockIdx.y * 128;
    const int bn = blockIdx.x * 128;
    const int t    = threadIdx.x;
    const int lane = t & 31;
    const int wid  = t >> 5;
    const int wm   = wid >> 1;        // 0..1 (M)
    const int wn   = wid & 1;         // 0..1 (N)
    const int g    = lane >> 2;       // 0..7
    const int tig  = lane & 3;        // 0..3

    uint32_t smem_base = (uint32_t)__cvta_generic_to_shared(smf);
    smem_base = (smem_base + 127u) & ~127u;

    if (mask && t == 0) {
        int is_int = 1;
        #pragma unroll 4
        for (int i = 0; i < 256; i++)
            if ((i & 3) != 0 && mask[i] != 0) is_int = 0;
        mask_is_int32 = is_int;
    }

    float acc[4][8][4];
    #pragma unroll
    for (int i = 0; i < 4; i++)
        #pragma unroll
        for (int j = 0; j < 8; j++)
            #pragma unroll
            for (int r = 0; r < 4; r++) acc[i][j][r] = 0.f;

    const int nkt = K / BK;

    // stage load: A,B tiles are 128 rows x 32 floats (128B rows), swizzled
    auto issue = [&](int kt) {
        const uint32_t abase = smem_base + (uint32_t)(kt % NSTAGE) * STG_B;
        const uint32_t bbase = abase + TILE_B;
        const float* gA = A + (size_t)bm * K + (size_t)kt * BK;
        const float* gB = B + (size_t)bn * K + (size_t)kt * BK;
        #pragma unroll
        for (int i = 0; i < 8; i++) {
            const int chunk = t + i * 128;          // 0..1023
            const int row = chunk >> 3, kc = chunk & 7;
            const uint32_t sw = sw128((uint32_t)(row * 128 + kc * 16));
            cpa16s(abase + sw, gA + (size_t)row * K + kc * 4);
            cpa16s(bbase + sw, gB + (size_t)row * K + kc * 4);
        }
        asm volatile("cp.async.commit_group;\n");
    };

    issue(0); issue(1);

    // ldmatrix per-lane selectors (constant across k-loop)
    const int a_row = (lane & 15);                       // row within 16-row group
    const int a_kof = (lane >> 4) << 2;                  // 0 or 4 floats
    const int b_row = (lane & 7) + ((lane & 16) >> 1);   // row within 16-n group
    const int b_kof = (lane & 8) >> 1;                   // 0 or 4 floats

    for (int kt = 0; kt < nkt; ++kt) {
        if (kt + 1 < nkt) asm volatile("cp.async.wait_group 1;\n");
        else              asm volatile("cp.async.wait_group 0;\n");
        __syncthreads();

        if (kt + 2 < nkt) issue(kt + 2);

        const uint32_t abase = smem_base + (uint32_t)(kt % NSTAGE) * STG_B;
        const uint32_t bbase = abase + TILE_B;

        #pragma unroll
        for (int ks = 0; ks < 4; ++ks) {
            const int k0 = ks * 8;
            uint32_t af[4][4];
            uint32_t bf[8][2];
            #pragma unroll
            for (int i = 0; i < 4; i++) {
                const int rb = wm * 64 + i * 16;
                const uint32_t off = (uint32_t)((rb + a_row) * 128 + (k0 + a_kof) * 4);
                ldmx4s(af[i], abase + sw128(off));
            }
            #pragma unroll
            for (int jp = 0; jp < 4; jp++) {
                uint32_t bq[4];
                const int nb = wn * 64 + jp * 16;
                const uint32_t off = (uint32_t)((nb + b_row) * 128 + (k0 + b_kof) * 4);
                ldmx4s(bq, bbase + sw128(off));
                bf[jp * 2][0]     = bq[0];
                bf[jp * 2][1]     = bq[1];
                bf[jp * 2 + 1][0] = bq[2];
                bf[jp * 2 + 1][1] = bq[3];
            }
            #pragma unroll
            for (int i = 0; i < 4; i++)
                #pragma unroll
                for (int j = 0; j < 8; j++)
                    mma8(acc[i][j], af[i], bf[j]);
        }
    }

    if (mask) __syncthreads();   // make mask_is_int32 visible

    // epilogue: warp covers 64x64 at (bm + wm*64, bn + wn*64)
    #pragma unroll
    for (int i = 0; i < 4; i++) {
        const int r0 = bm + wm * 64 + i * 16 + g;
        #pragma unroll
        for (int j = 0; j < 8; j++) {
            const int c0 = bn + wn * 64 + j * 8 + tig * 2;
            float v0 = acc[i][j][0], v1 = acc[i][j][1];
            float v2 = acc[i][j][2], v3 = acc[i][j][3];
            if (mask) {
                const size_t base = (size_t)bz * (size_t)M * N + (size_t)r0 * N;
                int m00, m01, m10, m11;
                if (mask_is_int32) {
                    const int* mi = (const int*)mask;
                    int2 ma = *(const int2*)&mi[base + c0];
                    int2 mb = *(const int2*)&mi[base + (size_t)8 * N + c0];
                    m00 = ma.x; m01 = ma.y; m10 = mb.x; m11 = mb.y;
                } else {
                    m00 = mask[base + c0];                   m01 = mask[base + c0 + 1];
                    m10 = mask[base + (size_t)8 * N + c0];   m11 = mask[base + (size_t)8 * N + c0 + 1];
                }
                v0 = m00 ? v0 * scale : -1e10f;
                v1 = m01 ? v1 * scale : -1e10f;
                v2 = m10 ? v2 * scale : -1e10f;
                v3 = m11 ? v3 * scale : -1e10f;
            }
            if (roundC) {
                v0 = rtf(v0); v1 = rtf(v1); v2 = rtf(v2); v3 = rtf(v3);
            }
            float2 w0 = {v0, v1}, w1 = {v2, v3};
            *(float2*)&C[(size_t)r0 * N + c0]       = w0;
            *(float2*)&C[(size_t)(r0 + 8) * N + c0] = w1;
        }
    }
}

// ---------------- softmax ----------------

__global__ void softmax2048(float* __restrict__ P)
{
    float* p = P + (size_t)blockIdx.x * 2048;
    const int t = threadIdx.x, lane = t & 31, wid = t >> 5;
    __shared__ float red[8];

    float4 v0 = ((const float4*)p)[t];
    float4 v1 = ((const float4*)p)[t + 256];

    float m = fmaxf(fmaxf(fmaxf(v0.x, v0.y), fmaxf(v0.z, v0.w)),
                    fmaxf(fmaxf(v1.x, v1.y), fmaxf(v1.z, v1.w)));
    #pragma unroll
    for (int o = 16; o; o >>= 1) m = fmaxf(m, __shfl_xor_sync(0xffffffffu, m, o));
    if (lane == 0) red[wid] = m;
    __syncthreads();
    float bm = red[0];
    #pragma unroll
    for (int w = 1; w < 8; w++) bm = fmaxf(bm, red[w]);
    __syncthreads();

    v0.x = __expf(v0.x - bm); v0.y = __expf(v0.y - bm);
    v0.z = __expf(v0.z - bm); v0.w = __expf(v0.w - bm);
    v1.x = __expf(v1.x - bm); v1.y = __expf(v1.y - bm);
    v1.z = __expf(v1.z - bm); v1.w = __expf(v1.w - bm);

    float s = v0.x + v0.y + v0.z + v0.w + v1.x + v1.y + v1.z + v1.w;
    #pragma unroll
    for (int o = 16; o; o >>= 1) s += __shfl_xor_sync(0xffffffffu, s, o);
    if (lane == 0) red[wid] = s;
    __syncthreads();
    float bs = red[0];
    #pragma unroll
    for (int w = 1; w < 8; w++) bs += red[w];

    const float inv = 1.f / bs;
    v0.x = rtf(v0.x * inv); v0.y = rtf(v0.y * inv);
    v0.z = rtf(v0.z * inv); v0.w = rtf(v0.w * inv);
    v1.x = rtf(v1.x * inv); v1.y = rtf(v1.y * inv);
    v1.z = rtf(v1.z * inv); v1.w = rtf(v1.w * inv);
    ((float4*)p)[t]       = v0;
    ((float4*)p)[t + 256] = v1;
}

// ---------------- host ----------------

extern "C" void kernel_launch(void* const* d_in, const int* in_sizes, int n_in,
                              void* d_out, int out_size)
{
    const float*         x    = (const float*)d_in[0];
    const unsigned char* mask = (const unsigned char*)d_in[1];
    const float*         Wq   = (const float*)d_in[2];
    const float*         Wk   = (const float*)d_in[3];
    const float*         Wv   = (const float*)d_in[4];
    const float*         Wo   = (const float*)d_in[5];
    float*               out  = (float*)d_out;

    float *QKV, *P, *AO, *X, *W, *VT;
    cudaGetSymbolAddress((void**)&QKV, g_QKV);
    cudaGetSymbolAddress((void**)&P,   g_P);
    cudaGetSymbolAddress((void**)&AO,  g_AO);
    cudaGetSymbolAddress((void**)&X,   g_X);
    cudaGetSymbolAddress((void**)&W,   g_W);
    cudaGetSymbolAddress((void**)&VT,  g_VT);

    const size_t pstride = (size_t)BATCH * SEQ * DMODEL;   // full Q/K/V plane
    const size_t bstride = (size_t)SEQ * DMODEL;           // per-batch plane
    const size_t wsz = (size_t)DMODEL * DMODEL;
    float* WqT = W;
    float* WkT = W + wsz;
    float* WvT = W + 2 * wsz;
    float* WoT = W + 3 * wsz;
    float* Q = QKV;
    float* Kp = QKV + pstride;
    float* V = QKV + 2 * pstride;

    // --- pre-pass: round x; transpose+round weights ---
    {
        const int xe4 = (int)(pstride / 4);
        round_tf32<<<(xe4 + 255) / 256, 256>>>((const float4*)x, (float4*)X, xe4);
        dim3 tb(32, 8);
        dim3 tg(DMODEL / 32, DMODEL / 32, 1);
        transpose_round<<<tg, tb>>>(Wq, WqT, DMODEL, DMODEL, 0, 0, 1);
        transpose_round<<<tg, tb>>>(Wk, WkT, DMODEL, DMODEL, 0, 0, 1);
        transpose_round<<<tg, tb>>>(Wv, WvT, DMODEL, DMODEL, 0, 0, 1);
        transpose_round<<<tg, tb>>>(Wo, WoT, DMODEL, DMODEL, 0, 0, 1);
    }

    const int smemB = 3 * 32768 + 128;   // 3 stages + alignment slack
    cudaFuncSetAttribute(gemm_nt<true>,
                         cudaFuncAttributeMaxDynamicSharedMemorySize, smemB);
    cudaFuncSetAttribute(gemm_nt<false>,
                         cudaFuncAttributeMaxDynamicSharedMemorySize, smemB);

    const int MS = BATCH * SEQ;   // 8192
    dim3 blk(128);

    // QKV projections fused: C[m,n] = X[m,k] * WT[n,k]
    dim3 gq(DMODEL / 128, MS / 128, 3);
    gemm_nt<true><<<gq, blk, smemB>>>(
        X, WqT, WkT, WvT, QKV, MS, DMODEL, DMODEL, 0, 0, pstride, nullptr, 1.f, 1);

    // V transpose per batch: VT[b][d][s] = V[b][s][d]
    {
        dim3 tb(32, 8);
        dim3 tg(DMODEL / 32, SEQ / 32, BATCH);
        transpose_round<<<tg, tb>>>(V, VT, SEQ, DMODEL, bstride, bstride, 0);
    }

    // scores = Q K^T / 32, masked
    dim3 gs(SEQ / 128, SEQ / 128, BATCH);
    gemm_nt<false><<<gs, blk, smemB>>>(
        Q, Kp, nullptr, nullptr, P, SEQ, SEQ, DMODEL,
        bstride, bstride, (size_t)SEQ * SEQ, mask, 0.03125f, 0);

    softmax2048<<<BATCH * SEQ, 256>>>(P);

    // attn_out = P * V  (B = VT[b] is [DMODEL rows, SEQ cols] K-major)
    dim3 gv(DMODEL / 128, SEQ / 128, BATCH);
    gemm_nt<false><<<gv, blk, smemB>>>(
        P, VT, nullptr, nullptr, AO, SEQ, DMODEL, SEQ,
        (size_t)SEQ * SEQ, bstride, bstride, nullptr, 1.f, 1);

    // output projection: out[m,n] = AO[m,k] * WoT[n,k]
    dim3 go(DMODEL / 128, MS / 128, 1);
    gemm_nt<false><<<go, blk, smemB>>>(
        AO, WoT, nullptr, nullptr, out, MS, DMODEL, DMODEL, 0, 0, 0, nullptr, 1.f, 0);
}

// round 9
// speedup vs baseline: 1.6666x; 1.1078x over previous
#include <cuda_runtime.h>
#include <cstdint>

#define BATCH 4
#define SEQ   2048
#define DMODEL 1024

// Scratch (device globals — no cudaMalloc allowed)
__device__ float g_QKV[(size_t)3 * BATCH * SEQ * DMODEL];   // 96 MB (Q,K,V)
__device__ float g_P  [(size_t)BATCH * SEQ * SEQ];          // 64 MB (scores/probs)
__device__ float g_AO [(size_t)BATCH * SEQ * DMODEL];       // 32 MB
__device__ float g_X  [(size_t)BATCH * SEQ * DMODEL];       // 32 MB (tf32-rounded x)
__device__ float g_W  [(size_t)4 * DMODEL * DMODEL];        // 16 MB (WqT,WkT,WvT,WoT rounded)
__device__ float g_VT [(size_t)BATCH * SEQ * DMODEL];       // 32 MB (V transposed per batch)

__device__ __forceinline__ uint32_t f2tf32(float x) {
    uint32_t r;
    asm("cvt.rna.tf32.f32 %0, %1;" : "=r"(r) : "f"(x));
    return r;
}
__device__ __forceinline__ float rtf(float x) { return __uint_as_float(f2tf32(x)); }

__device__ __forceinline__ void mma8(float c[4], const uint32_t a[4], const uint32_t b[2]) {
    asm volatile(
        "mma.sync.aligned.m16n8k8.row.col.f32.tf32.tf32.f32 "
        "{%0,%1,%2,%3}, {%4,%5,%6,%7}, {%8,%9}, {%0,%1,%2,%3};\n"
        : "+f"(c[0]), "+f"(c[1]), "+f"(c[2]), "+f"(c[3])
        : "r"(a[0]), "r"(a[1]), "r"(a[2]), "r"(a[3]), "r"(b[0]), "r"(b[1]));
}

__device__ __forceinline__ void cpa16s(uint32_t dst, const float* src) {
    asm volatile("cp.async.cg.shared.global [%0], [%1], 16;\n" :: "r"(dst), "l"(src));
}

__device__ __forceinline__ void ldmx4s(uint32_t r[4], uint32_t addr) {
    asm volatile("ldmatrix.sync.aligned.m8n8.x4.shared.b16 {%0,%1,%2,%3}, [%4];"
        : "=r"(r[0]), "=r"(r[1]), "=r"(r[2]), "=r"(r[3]) : "r"(addr));
}

// SW128-style XOR swizzle on byte offsets (16B granular): chunk ^= row%8
__device__ __forceinline__ uint32_t sw128(uint32_t off) {
    return off ^ ((off >> 3) & 0x70u);
}

// ---------------- pre-pass kernels ----------------

__global__ void round_tf32(const float4* __restrict__ in, float4* __restrict__ out, int n4)
{
    int i = blockIdx.x * blockDim.x + threadIdx.x;
    if (i < n4) {
        float4 v = in[i];
        v.x = rtf(v.x); v.y = rtf(v.y); v.z = rtf(v.z); v.w = rtf(v.w);
        out[i] = v;
    }
}

// Fused 4-weight transpose+round: z selects source W; out plane z.
__global__ void transpose_round_w(const float* __restrict__ W0, const float* __restrict__ W1,
                                  const float* __restrict__ W2, const float* __restrict__ W3,
                                  float* __restrict__ out)
{
    __shared__ float tile[32][33];
    const int z = blockIdx.z;
    const float* in = (z == 0) ? W0 : (z == 1) ? W1 : (z == 2) ? W2 : W3;
    out += (size_t)z * DMODEL * DMODEL;
    const int bx = blockIdx.x * 32;   // c
    const int by = blockIdx.y * 32;   // r
    const int tx = threadIdx.x, ty = threadIdx.y;
    #pragma unroll
    for (int i = 0; i < 32; i += 8)
        tile[ty + i][tx] = in[(size_t)(by + ty + i) * DMODEL + bx + tx];
    __syncthreads();
    #pragma unroll
    for (int i = 0; i < 32; i += 8)
        out[(size_t)(bx + ty + i) * DMODEL + by + tx] = rtf(tile[tx][ty + i]);
}

// out[c*R + r] = in[r*C + c]; batch planes via blockIdx.z (V transpose).
__global__ void transpose_plain(const float* __restrict__ in, float* __restrict__ out,
                                int R, int C, size_t sIn, size_t sOut)
{
    __shared__ float tile[32][33];
    in  += (size_t)blockIdx.z * sIn;
    out += (size_t)blockIdx.z * sOut;
    const int bx = blockIdx.x * 32;
    const int by = blockIdx.y * 32;
    const int tx = threadIdx.x, ty = threadIdx.y;
    #pragma unroll
    for (int i = 0; i < 32; i += 8)
        tile[ty + i][tx] = in[(size_t)(by + ty + i) * C + bx + tx];
    __syncthreads();
    #pragma unroll
    for (int i = 0; i < 32; i += 8)
        out[(size_t)(bx + ty + i) * R + by + tx] = tile[tx][ty + i];
}

// ---------------- NT TF32 GEMM: C[M,N] = A[M,K] * B[N,K]^T ----------------
// CTA tile 128x128x32, 4 warps (2x2), warp tile 64x64, 3-stage cp.async,
// XOR-swizzled smem (32KB/stage), ldmatrix fragments (register double-buffered),
// inputs pre-rounded to tf32.
//   TRIPLE: blockIdx.z selects B among {B0,B1,B2}, C += z*sC (QKV fusion)
//   mask: epilogue v*scale, masked -> -1e10 (int32 vs byte auto-probe)
//   roundC: round outputs to tf32.
template<bool TRIPLE>
__global__ __launch_bounds__(128, 2)
void gemm_nt(const float* __restrict__ A, const float* __restrict__ B0,
             const float* __restrict__ B1, const float* __restrict__ B2,
             float* __restrict__ C, int M, int N, int K,
             size_t sA, size_t sB, size_t sC,
             const unsigned char* __restrict__ mask, float scale, int roundC)
{
    constexpr int BK = 32;
    constexpr uint32_t TILE_B = 128u * 128u;     // 16 KB per operand tile
    constexpr uint32_t STG_B  = 2u * TILE_B;     // 32 KB per stage
    constexpr int NSTAGE = 3;

    extern __shared__ float smf[];
    __shared__ int mask_is_int32;

    const int bz = blockIdx.z;
    const float* B;
    if (TRIPLE) {
        B = (bz == 0) ? B0 : (bz == 1 ? B1 : B2);
        C += (size_t)bz * sC;
    } else {
        B = B0 + (size_t)bz * sB;
        A += (size_t)bz * sA;
        C += (size_t)bz * sC;
    }

    const int bm = blockIdx.y * 128;
    const int bn = blockIdx.x * 128;
    const int t    = threadIdx.x;
    const int lane = t & 31;
    const int wid  = t >> 5;
    const int wm   = wid >> 1;        // 0..1 (M)
    const int wn   = wid & 1;         // 0..1 (N)
    const int g    = lane >> 2;       // 0..7
    const int tig  = lane & 3;        // 0..3

    uint32_t smem_base = (uint32_t)__cvta_generic_to_shared(smf);
    smem_base = (smem_base + 127u) & ~127u;

    if (mask && t == 0) {
        int is_int = 1;
        #pragma unroll 4
        for (int i = 0; i < 256; i++)
            if ((i & 3) != 0 && mask[i] != 0) is_int = 0;
        mask_is_int32 = is_int;
    }

    float acc[4][8][4];
    #pragma unroll
    for (int i = 0; i < 4; i++)
        #pragma unroll
        for (int j = 0; j < 8; j++)
            #pragma unroll
            for (int r = 0; r < 4; r++) acc[i][j][r] = 0.f;

    const int nkt = K / BK;

    auto issue = [&](int kt) {
        const uint32_t abase = smem_base + (uint32_t)(kt % NSTAGE) * STG_B;
        const uint32_t bbase = abase + TILE_B;
        const float* gA = A + (size_t)bm * K + (size_t)kt * BK;
        const float* gB = B + (size_t)bn * K + (size_t)kt * BK;
        #pragma unroll
        for (int i = 0; i < 8; i++) {
            const int chunk = t + i * 128;          // 0..1023
            const int row = chunk >> 3, kc = chunk & 7;
            const uint32_t sw = sw128((uint32_t)(row * 128 + kc * 16));
            cpa16s(abase + sw, gA + (size_t)row * K + kc * 4);
            cpa16s(bbase + sw, gB + (size_t)row * K + kc * 4);
        }
        asm volatile("cp.async.commit_group;\n");
    };

    issue(0); issue(1);

    // ldmatrix per-lane selectors (constant across k-loop)
    const int a_row = (lane & 15);                       // row within 16-row group
    const int a_kof = (lane >> 4) << 2;                  // 0 or 4 floats
    const int b_row = (lane & 7) + ((lane & 16) >> 1);   // row within 16-n group
    const int b_kof = (lane & 8) >> 1;                   // 0 or 4 floats

    // double-buffered fragments
    uint32_t af[2][4][4];
    uint32_t bf[2][8][2];

    for (int kt = 0; kt < nkt; ++kt) {
        if (kt + 1 < nkt) asm volatile("cp.async.wait_group 1;\n");
        else              asm volatile("cp.async.wait_group 0;\n");
        __syncthreads();

        const uint32_t abase = smem_base + (uint32_t)(kt % NSTAGE) * STG_B;
        const uint32_t bbase = abase + TILE_B;

        auto ldfrag = [&](int ks, int buf) {
            const int k0 = ks * 8;
            #pragma unroll
            for (int i = 0; i < 4; i++) {
                const int rb = wm * 64 + i * 16;
                const uint32_t off = (uint32_t)((rb + a_row) * 128 + (k0 + a_kof) * 4);
                ldmx4s(af[buf][i], abase + sw128(off));
            }
            #pragma unroll
            for (int jp = 0; jp < 4; jp++) {
                uint32_t bq[4];
                const int nb = wn * 64 + jp * 16;
                const uint32_t off = (uint32_t)((nb + b_row) * 128 + (k0 + b_kof) * 4);
                ldmx4s(bq, bbase + sw128(off));
                bf[buf][jp * 2][0]     = bq[0];
                bf[buf][jp * 2][1]     = bq[1];
                bf[buf][jp * 2 + 1][0] = bq[2];
                bf[buf][jp * 2 + 1][1] = bq[3];
            }
        };

        ldfrag(0, 0);
        if (kt + 2 < nkt) issue(kt + 2);   // overlap LSU with first compute

        #pragma unroll
        for (int ks = 0; ks < 4; ++ks) {
            const int cur = ks & 1;
            if (ks < 3) ldfrag(ks + 1, cur ^ 1);
            #pragma unroll
            for (int i = 0; i < 4; i++)
                #pragma unroll
                for (int j = 0; j < 8; j++)
                    mma8(acc[i][j], af[cur][i], bf[cur][j]);
        }
    }

    // epilogue: warp covers 64x64 at (bm + wm*64, bn + wn*64)
    // (mask_is_int32 visibility is ordered by the mainloop __syncthreads)
    #pragma unroll
    for (int i = 0; i < 4; i++) {
        const int r0 = bm + wm * 64 + i * 16 + g;
        #pragma unroll
        for (int j = 0; j < 8; j++) {
            const int c0 = bn + wn * 64 + j * 8 + tig * 2;
            float v0 = acc[i][j][0], v1 = acc[i][j][1];
            float v2 = acc[i][j][2], v3 = acc[i][j][3];
            if (mask) {
                const size_t base = (size_t)bz * (size_t)M * N + (size_t)r0 * N;
                int m00, m01, m10, m11;
                if (mask_is_int32) {
                    const int* mi = (const int*)mask;
                    int2 ma = *(const int2*)&mi[base + c0];
                    int2 mb = *(const int2*)&mi[base + (size_t)8 * N + c0];
                    m00 = ma.x; m01 = ma.y; m10 = mb.x; m11 = mb.y;
                } else {
                    m00 = mask[base + c0];                   m01 = mask[base + c0 + 1];
                    m10 = mask[base + (size_t)8 * N + c0];   m11 = mask[base + (size_t)8 * N + c0 + 1];
                }
                v0 = m00 ? v0 * scale : -1e10f;
                v1 = m01 ? v1 * scale : -1e10f;
                v2 = m10 ? v2 * scale : -1e10f;
                v3 = m11 ? v3 * scale : -1e10f;
            }
            if (roundC) {
                v0 = rtf(v0); v1 = rtf(v1); v2 = rtf(v2); v3 = rtf(v3);
            }
            float2 w0 = {v0, v1}, w1 = {v2, v3};
            *(float2*)&C[(size_t)r0 * N + c0]       = w0;
            *(float2*)&C[(size_t)(r0 + 8) * N + c0] = w1;
        }
    }
}

// ---------------- softmax ----------------

__global__ void softmax2048(float* __restrict__ P)
{
    float* p = P + (size_t)blockIdx.x * 2048;
    const int t = threadIdx.x, lane = t & 31, wid = t >> 5;
    __shared__ float red[8];

    float4 v0 = ((const float4*)p)[t];
    float4 v1 = ((const float4*)p)[t + 256];

    float m = fmaxf(fmaxf(fmaxf(v0.x, v0.y), fmaxf(v0.z, v0.w)),
                    fmaxf(fmaxf(v1.x, v1.y), fmaxf(v1.z, v1.w)));
    #pragma unroll
    for (int o = 16; o; o >>= 1) m = fmaxf(m, __shfl_xor_sync(0xffffffffu, m, o));
    if (lane == 0) red[wid] = m;
    __syncthreads();
    float bm = red[0];
    #pragma unroll
    for (int w = 1; w < 8; w++) bm = fmaxf(bm, red[w]);
    __syncthreads();

    v0.x = __expf(v0.x - bm); v0.y = __expf(v0.y - bm);
    v0.z = __expf(v0.z - bm); v0.w = __expf(v0.w - bm);
    v1.x = __expf(v1.x - bm); v1.y = __expf(v1.y - bm);
    v1.z = __expf(v1.z - bm); v1.w = __expf(v1.w - bm);

    float s = v0.x + v0.y + v0.z + v0.w + v1.x + v1.y + v1.z + v1.w;
    #pragma unroll
    for (int o = 16; o; o >>= 1) s += __shfl_xor_sync(0xffffffffu, s, o);
    if (lane == 0) red[wid] = s;
    __syncthreads();
    float bs = red[0];
    #pragma unroll
    for (int w = 1; w < 8; w++) bs += red[w];

    const float inv = 1.f / bs;
    v0.x = rtf(v0.x * inv); v0.y = rtf(v0.y * inv);
    v0.z = rtf(v0.z * inv); v0.w = rtf(v0.w * inv);
    v1.x = rtf(v1.x * inv); v1.y = rtf(v1.y * inv);
    v1.z = rtf(v1.z * inv); v1.w = rtf(v1.w * inv);
    ((float4*)p)[t]       = v0;
    ((float4*)p)[t + 256] = v1;
}

// ---------------- host ----------------

extern "C" void kernel_launch(void* const* d_in, const int* in_sizes, int n_in,
                              void* d_out, int out_size)
{
    const float*         x    = (const float*)d_in[0];
    const unsigned char* mask = (const unsigned char*)d_in[1];
    const float*         Wq   = (const float*)d_in[2];
    const float*         Wk   = (const float*)d_in[3];
    const float*         Wv   = (const float*)d_in[4];
    const float*         Wo   = (const float*)d_in[5];
    float*               out  = (float*)d_out;

    float *QKV, *P, *AO, *X, *W, *VT;
    cudaGetSymbolAddress((void**)&QKV, g_QKV);
    cudaGetSymbolAddress((void**)&P,   g_P);
    cudaGetSymbolAddress((void**)&AO,  g_AO);
    cudaGetSymbolAddress((void**)&X,   g_X);
    cudaGetSymbolAddress((void**)&W,   g_W);
    cudaGetSymbolAddress((void**)&VT,  g_VT);

    const size_t pstride = (size_t)BATCH * SEQ * DMODEL;   // full Q/K/V plane
    const size_t bstride = (size_t)SEQ * DMODEL;           // per-batch plane
    const size_t wsz = (size_t)DMODEL * DMODEL;
    float* WqT = W;
    float* WkT = W + wsz;
    float* WvT = W + 2 * wsz;
    float* WoT = W + 3 * wsz;
    float* Q = QKV;
    float* Kp = QKV + pstride;
    float* V = QKV + 2 * pstride;

    // --- pre-pass: round x; fused transpose+round of all weights ---
    {
        const int xe4 = (int)(pstride / 4);
        round_tf32<<<(xe4 + 255) / 256, 256>>>((const float4*)x, (float4*)X, xe4);
        dim3 tb(32, 8);
        dim3 tgw(DMODEL / 32, DMODEL / 32, 4);
        transpose_round_w<<<tgw, tb>>>(Wq, Wk, Wv, Wo, W);
    }

    const int smemB = 3 * 32768 + 128;   // 3 stages + alignment slack
    cudaFuncSetAttribute(gemm_nt<true>,
                         cudaFuncAttributeMaxDynamicSharedMemorySize, smemB);
    cudaFuncSetAttribute(gemm_nt<false>,
                         cudaFuncAttributeMaxDynamicSharedMemorySize, smemB);

    const int MS = BATCH * SEQ;   // 8192
    dim3 blk(128);

    // QKV projections fused: C[m,n] = X[m,k] * WT[n,k]
    dim3 gq(DMODEL / 128, MS / 128, 3);
    gemm_nt<true><<<gq, blk, smemB>>>(
        X, WqT, WkT, WvT, QKV, MS, DMODEL, DMODEL, 0, 0, pstride, nullptr, 1.f, 1);

    // V transpose per batch: VT[b][d][s] = V[b][s][d]
    {
        dim3 tb(32, 8);
        dim3 tg(DMODEL / 32, SEQ / 32, BATCH);
        transpose_plain<<<tg, tb>>>(V, VT, SEQ, DMODEL, bstride, bstride);
    }

    // scores = Q K^T / 32, masked
    dim3 gs(SEQ / 128, SEQ / 128, BATCH);
    gemm_nt<false><<<gs, blk, smemB>>>(
        Q, Kp, nullptr, nullptr, P, SEQ, SEQ, DMODEL,
        bstride, bstride, (size_t)SEQ * SEQ, mask, 0.03125f, 0);

    softmax2048<<<BATCH * SEQ, 256>>>(P);

    // attn_out = P * V  (B = VT[b] is [DMODEL rows, SEQ cols] K-major)
    dim3 gv(DMODEL / 128, SEQ / 128, BATCH);
    gemm_nt<false><<<gv, blk, smemB>>>(
        P, VT, nullptr, nullptr, AO, SEQ, DMODEL, SEQ,
        (size_t)SEQ * SEQ, bstride, bstride, nullptr, 1.f, 1);

    // output projection: out[m,n] = AO[m,k] * WoT[n,k]
    dim3 go(DMODEL / 128, MS / 128, 1);
    gemm_nt<false><<<go, blk, smemB>>>(
        AO, WoT, nullptr, nullptr, out, MS, DMODEL, DMODEL, 0, 0, 0, nullptr, 1.f, 0);
}